// round 8
// baseline (speedup 1.0000x reference)
#include <cuda_runtime.h>
#include <cstdint>

// Problem constants (fixed by the reference)
#define NN 100000
#define NF 512
#define NH 128
#define NC 40
#define EMAX 3200000

// Scratch (device globals; no allocation allowed)
__device__ float  g_supp1[NN * NH];     // x @ W1          51.2 MB
__device__ float  g_supp2[NN * NC];     // x2 @ W2         16 MB
__device__ float2 g_edges[EMAX];        // CSR (col,w)     25.6 MB
__device__ int    g_rowptr[NN + 1];
__device__ int    g_cursor[NN];
__device__ int    g_deg[NN];

// Side stream + fork/join events, created at program init.
static cudaStream_t g_s1 = nullptr;
static cudaEvent_t  g_ev_fork = nullptr, g_ev_join = nullptr;
namespace {
struct StreamInit {
    StreamInit() {
        cudaStreamCreateWithFlags(&g_s1, cudaStreamNonBlocking);
        cudaEventCreateWithFlags(&g_ev_fork, cudaEventDisableTiming);
        cudaEventCreateWithFlags(&g_ev_join, cudaEventDisableTiming);
    }
};
static StreamInit g_stream_init;
}

// ---------------------------------------------------------------------------
// f32x2 packed helpers
// ---------------------------------------------------------------------------
typedef unsigned long long ull;

__device__ __forceinline__ ull ffma2(ull a, ull b, ull c) {
    ull d;
    asm("fma.rn.f32x2 %0, %1, %2, %3;" : "=l"(d) : "l"(a), "l"(b), "l"(c));
    return d;
}
__device__ __forceinline__ ull pack2(float lo, float hi) {
    ull d;
    asm("mov.b64 %0, {%1, %2};" : "=l"(d) : "f"(lo), "f"(hi));
    return d;
}
__device__ __forceinline__ void unpack2(ull v, float& lo, float& hi) {
    asm("mov.b64 {%0, %1}, %2;" : "=f"(lo), "=f"(hi) : "l"(v));
}

// ---------------------------------------------------------------------------
// GEMM1 (packed FFMA2): supp1[N,128] = x[N,512] @ W1[512,128]
// ---------------------------------------------------------------------------
#define AT_PAD 130
#define BS_PAD 132

__global__ __launch_bounds__(256) void gemm1_kernel(
    const float* __restrict__ x, const float* __restrict__ W1,
    float* __restrict__ out)
{
    __shared__ float As_t[16][AT_PAD];   // [k][row]
    __shared__ float Bs[16][BS_PAD];     // [k][col]

    const int t = threadIdx.x;
    const int wid = t >> 5, lane = t & 31;
    const int warp_m = wid & 3;
    const int warp_n = wid >> 2;
    const int r0 = warp_m * 32 + (lane & 3) * 8;
    const int c0 = warp_n * 64 + (lane >> 2) * 8;
    const int block_row = blockIdx.x * 128;

    ull acc[4][8];
#pragma unroll
    for (int p = 0; p < 4; p++)
#pragma unroll
        for (int c = 0; c < 8; c++) acc[p][c] = 0ULL;

    for (int k0 = 0; k0 < NF; k0 += 16) {
#pragma unroll
        for (int j = 0; j < 2; j++) {
            int i = t + j * 256;
            int r = i >> 2;
            int kq = (i & 3) << 2;
            float4 v = make_float4(0.f, 0.f, 0.f, 0.f);
            if (block_row + r < NN)
                v = *(const float4*)&x[(size_t)(block_row + r) * NF + k0 + kq];
            As_t[kq + 0][r] = v.x;
            As_t[kq + 1][r] = v.y;
            As_t[kq + 2][r] = v.z;
            As_t[kq + 3][r] = v.w;
        }
#pragma unroll
        for (int j = 0; j < 2; j++) {
            int i = t + j * 256;
            int kk = i >> 5;
            int c = (i & 31) << 2;
            *(float4*)&Bs[kk][c] = *(const float4*)&W1[(size_t)(k0 + kk) * NH + c];
        }
        __syncthreads();

#pragma unroll
        for (int kk = 0; kk < 16; kk++) {
            ull a2[4];
#pragma unroll
            for (int p = 0; p < 4; p++)
                a2[p] = *(const ull*)&As_t[kk][r0 + p * 2];

            float4 b04 = *(const float4*)&Bs[kk][c0];
            float4 b48 = *(const float4*)&Bs[kk][c0 + 4];
            ull b2[8];
            b2[0] = pack2(b04.x, b04.x); b2[1] = pack2(b04.y, b04.y);
            b2[2] = pack2(b04.z, b04.z); b2[3] = pack2(b04.w, b04.w);
            b2[4] = pack2(b48.x, b48.x); b2[5] = pack2(b48.y, b48.y);
            b2[6] = pack2(b48.z, b48.z); b2[7] = pack2(b48.w, b48.w);

#pragma unroll
            for (int p = 0; p < 4; p++)
#pragma unroll
                for (int c = 0; c < 8; c++)
                    acc[p][c] = ffma2(a2[p], b2[c], acc[p][c]);
        }
        __syncthreads();
    }

#pragma unroll
    for (int p = 0; p < 4; p++) {
        float lo[8], hi[8];
#pragma unroll
        for (int c = 0; c < 8; c++) unpack2(acc[p][c], lo[c], hi[c]);
        int gr0 = block_row + r0 + p * 2;
        int gr1 = gr0 + 1;
        if (gr0 < NN) {
            *(float4*)&out[(size_t)gr0 * NH + c0]     = make_float4(lo[0], lo[1], lo[2], lo[3]);
            *(float4*)&out[(size_t)gr0 * NH + c0 + 4] = make_float4(lo[4], lo[5], lo[6], lo[7]);
        }
        if (gr1 < NN) {
            *(float4*)&out[(size_t)gr1 * NH + c0]     = make_float4(hi[0], hi[1], hi[2], hi[3]);
            *(float4*)&out[(size_t)gr1 * NH + c0 + 4] = make_float4(hi[4], hi[5], hi[6], hi[7]);
        }
    }
}

// ---------------------------------------------------------------------------
// CSR build
// ---------------------------------------------------------------------------
__global__ void zero_deg_kernel(int* __restrict__ deg)
{
    int i = blockIdx.x * blockDim.x + threadIdx.x;
    if (i < NN) deg[i] = 0;
}

__global__ void hist_kernel(const int* __restrict__ er, int* __restrict__ deg, int E)
{
    int e = (blockIdx.x * blockDim.x + threadIdx.x) * 2;
    if (e + 1 < E) {
        int2 r2 = *(const int2*)&er[e];
        atomicAdd(&deg[r2.x], 1);
        atomicAdd(&deg[r2.y], 1);
    } else if (e < E) {
        atomicAdd(&deg[er[e]], 1);
    }
}

// exclusive scan over deg -> rowptr/cursor, single block, warp-shfl based.
__global__ __launch_bounds__(1024) void scan_kernel(
    const int* __restrict__ deg, int* __restrict__ rowptr,
    int* __restrict__ cursor)
{
    __shared__ int wsum[32];
    __shared__ int carry_s;
    const int t = threadIdx.x, lane = t & 31, w = t >> 5;
    if (t == 0) carry_s = 0;
    __syncthreads();

    for (int base = 0; base < NN; base += 4096) {
        int cbase = carry_s;
        int i = base + t * 4;
        int4 v = make_int4(0, 0, 0, 0);
        if (i < NN) v = *(const int4*)&deg[i];   // NN % 4 == 0
        int s = v.x + v.y + v.z + v.w;

        int inc = s;
#pragma unroll
        for (int o = 1; o < 32; o <<= 1) {
            int y = __shfl_up_sync(0xffffffffu, inc, o);
            if (lane >= o) inc += y;
        }
        if (lane == 31) wsum[w] = inc;
        __syncthreads();
        if (w == 0) {
            int ws = wsum[lane];
#pragma unroll
            for (int o = 1; o < 32; o <<= 1) {
                int y = __shfl_up_sync(0xffffffffu, ws, o);
                if (lane >= o) ws += y;
            }
            wsum[lane] = ws;
        }
        __syncthreads();

        int prefix = cbase + ((w > 0) ? wsum[w - 1] : 0) + (inc - s);
        if (i < NN) {
            int e0 = prefix;
            int e1 = e0 + v.x;
            int e2 = e1 + v.y;
            int e3 = e2 + v.z;
            int4 o4 = make_int4(e0, e1, e2, e3);
            *(int4*)&rowptr[i] = o4;
            *(int4*)&cursor[i] = o4;
        }
        __syncthreads();
        if (t == 0) carry_s += wsum[31];
        __syncthreads();
    }
    if (t == 0) rowptr[NN] = carry_s;
}

__global__ void scatter_kernel(
    const int* __restrict__ er, const int* __restrict__ ec,
    const float* __restrict__ ew, int* __restrict__ cursor,
    float2* __restrict__ edges, int E)
{
    int e = (blockIdx.x * blockDim.x + threadIdx.x) * 2;
    if (e + 1 < E) {
        int2   r2 = *(const int2*)&er[e];
        int2   c2 = *(const int2*)&ec[e];
        float2 w2 = *(const float2*)&ew[e];
        int p0 = atomicAdd(&cursor[r2.x], 1);
        edges[p0] = make_float2(__int_as_float(c2.x), w2.x);
        int p1 = atomicAdd(&cursor[r2.y], 1);
        edges[p1] = make_float2(__int_as_float(c2.y), w2.y);
    } else if (e < E) {
        int pos = atomicAdd(&cursor[er[e]], 1);
        edges[pos] = make_float2(__int_as_float(ec[e]), ew[e]);
    }
}

// ---------------------------------------------------------------------------
// SpMM1-CSR fused with bias + relu + dropout mask (8-edge unroll)
// ---------------------------------------------------------------------------
__global__ __launch_bounds__(256) void spmm1_csr_kernel(
    const int* __restrict__ rowptr, const float2* __restrict__ edges,
    const float4* __restrict__ suppv, const float* __restrict__ b1,
    const float* __restrict__ mask, float* __restrict__ x2)
{
    const int warp = (blockIdx.x * blockDim.x + threadIdx.x) >> 5;
    if (warp >= NN) return;
    const int lane = threadIdx.x & 31;

    const int s = __ldg(&rowptr[warp]);
    const int e = __ldg(&rowptr[warp + 1]);

    float4 acc = make_float4(0.f, 0.f, 0.f, 0.f);
    int i = s;
    for (; i + 8 <= e; i += 8) {
        float2 ed[8];
#pragma unroll
        for (int u = 0; u < 8; u++) ed[u] = __ldg(&edges[i + u]);
        float4 g[8];
#pragma unroll
        for (int u = 0; u < 8; u++)
            g[u] = __ldg(&suppv[(size_t)__float_as_int(ed[u].x) * (NH / 4) + lane]);
#pragma unroll
        for (int u = 0; u < 8; u++) {
            acc.x = fmaf(ed[u].y, g[u].x, acc.x);
            acc.y = fmaf(ed[u].y, g[u].y, acc.y);
            acc.z = fmaf(ed[u].y, g[u].z, acc.z);
            acc.w = fmaf(ed[u].y, g[u].w, acc.w);
        }
    }
    for (; i + 2 <= e; i += 2) {
        float2 ed0 = __ldg(&edges[i]);
        float2 ed1 = __ldg(&edges[i + 1]);
        float4 g0 = __ldg(&suppv[(size_t)__float_as_int(ed0.x) * (NH / 4) + lane]);
        float4 g1 = __ldg(&suppv[(size_t)__float_as_int(ed1.x) * (NH / 4) + lane]);
        acc.x = fmaf(ed0.y, g0.x, acc.x); acc.y = fmaf(ed0.y, g0.y, acc.y);
        acc.z = fmaf(ed0.y, g0.z, acc.z); acc.w = fmaf(ed0.y, g0.w, acc.w);
        acc.x = fmaf(ed1.y, g1.x, acc.x); acc.y = fmaf(ed1.y, g1.y, acc.y);
        acc.z = fmaf(ed1.y, g1.z, acc.z); acc.w = fmaf(ed1.y, g1.w, acc.w);
    }
    if (i < e) {
        float2 ed = __ldg(&edges[i]);
        float4 g = __ldg(&suppv[(size_t)__float_as_int(ed.x) * (NH / 4) + lane]);
        acc.x = fmaf(ed.y, g.x, acc.x); acc.y = fmaf(ed.y, g.y, acc.y);
        acc.z = fmaf(ed.y, g.z, acc.z); acc.w = fmaf(ed.y, g.w, acc.w);
    }

    float4 bb = *(const float4*)&b1[lane << 2];
    float4 mm = *(const float4*)&mask[(size_t)warp * NH + (lane << 2)];
    float4 r;
    r.x = fmaxf(acc.x + bb.x, 0.f) * mm.x;
    r.y = fmaxf(acc.y + bb.y, 0.f) * mm.y;
    r.z = fmaxf(acc.z + bb.z, 0.f) * mm.z;
    r.w = fmaxf(acc.w + bb.w, 0.f) * mm.w;
    *(float4*)&x2[(size_t)warp * NH + (lane << 2)] = r;
}

// ---------------------------------------------------------------------------
// GEMM2: supp2[N,40] = x2[N,128] @ W2[128,40]. Warp-per-row, W2 in smem.
// ---------------------------------------------------------------------------
__global__ __launch_bounds__(256) void gemm2_kernel(
    const float* __restrict__ x2, const float* __restrict__ W2,
    float* __restrict__ out)
{
    __shared__ float sW2[NH * NC];  // 20 KB
    for (int i = threadIdx.x; i < NH * NC; i += blockDim.x) sW2[i] = W2[i];
    __syncthreads();

    const int lane = threadIdx.x & 31;
    const int wid  = threadIdx.x >> 5;
    const int row  = blockIdx.x * 8 + wid;
    if (row >= NN) return;

    float acc1 = 0.0f, acc2 = 0.0f;
    const float* xr = &x2[(size_t)row * NH];
#pragma unroll 8
    for (int k = 0; k < NH; k++) {
        float xv = xr[k];
        acc1 = fmaf(xv, sW2[k * NC + lane], acc1);
        if (lane < 8) acc2 = fmaf(xv, sW2[k * NC + 32 + lane], acc2);
    }
    out[(size_t)row * NC + lane] = acc1;
    if (lane < 8) out[(size_t)row * NC + 32 + lane] = acc2;
}

// ---------------------------------------------------------------------------
// SpMM2-CSR fused with bias + log_softmax (4-edge unroll)
// ---------------------------------------------------------------------------
__global__ __launch_bounds__(256) void spmm2_lsm_kernel(
    const int* __restrict__ rowptr, const float2* __restrict__ edges,
    const float4* __restrict__ suppv, const float* __restrict__ b2,
    float* __restrict__ out)
{
    const int warp = (blockIdx.x * blockDim.x + threadIdx.x) >> 5;
    if (warp >= NN) return;
    const int lane = threadIdx.x & 31;
    const bool act = (lane < NC / 4);

    const int s = __ldg(&rowptr[warp]);
    const int e = __ldg(&rowptr[warp + 1]);

    float4 acc = make_float4(0.f, 0.f, 0.f, 0.f);
    int i = s;
    for (; i + 4 <= e; i += 4) {
        float2 ed0 = __ldg(&edges[i]);
        float2 ed1 = __ldg(&edges[i + 1]);
        float2 ed2 = __ldg(&edges[i + 2]);
        float2 ed3 = __ldg(&edges[i + 3]);
        if (act) {
            float4 g0 = __ldg(&suppv[(size_t)__float_as_int(ed0.x) * (NC / 4) + lane]);
            float4 g1 = __ldg(&suppv[(size_t)__float_as_int(ed1.x) * (NC / 4) + lane]);
            float4 g2 = __ldg(&suppv[(size_t)__float_as_int(ed2.x) * (NC / 4) + lane]);
            float4 g3 = __ldg(&suppv[(size_t)__float_as_int(ed3.x) * (NC / 4) + lane]);
            acc.x = fmaf(ed0.y, g0.x, acc.x); acc.y = fmaf(ed0.y, g0.y, acc.y);
            acc.z = fmaf(ed0.y, g0.z, acc.z); acc.w = fmaf(ed0.y, g0.w, acc.w);
            acc.x = fmaf(ed1.y, g1.x, acc.x); acc.y = fmaf(ed1.y, g1.y, acc.y);
            acc.z = fmaf(ed1.y, g1.z, acc.z); acc.w = fmaf(ed1.y, g1.w, acc.w);
            acc.x = fmaf(ed2.y, g2.x, acc.x); acc.y = fmaf(ed2.y, g2.y, acc.y);
            acc.z = fmaf(ed2.y, g2.z, acc.z); acc.w = fmaf(ed2.y, g2.w, acc.w);
            acc.x = fmaf(ed3.y, g3.x, acc.x); acc.y = fmaf(ed3.y, g3.y, acc.y);
            acc.z = fmaf(ed3.y, g3.z, acc.z); acc.w = fmaf(ed3.y, g3.w, acc.w);
        }
    }
    for (; i < e; i++) {
        float2 ed = __ldg(&edges[i]);
        if (act) {
            float4 g = __ldg(&suppv[(size_t)__float_as_int(ed.x) * (NC / 4) + lane]);
            acc.x = fmaf(ed.y, g.x, acc.x); acc.y = fmaf(ed.y, g.y, acc.y);
            acc.z = fmaf(ed.y, g.z, acc.z); acc.w = fmaf(ed.y, g.w, acc.w);
        }
    }

    float4 v = make_float4(0.f, 0.f, 0.f, 0.f);
    float m = -3.4e38f;
    if (act) {
        float4 bb = *(const float4*)&b2[lane << 2];
        v.x = acc.x + bb.x; v.y = acc.y + bb.y;
        v.z = acc.z + bb.z; v.w = acc.w + bb.w;
        m = fmaxf(fmaxf(v.x, v.y), fmaxf(v.z, v.w));
    }
#pragma unroll
    for (int o = 16; o > 0; o >>= 1)
        m = fmaxf(m, __shfl_xor_sync(0xffffffffu, m, o));

    float sum = 0.f;
    if (act)
        sum = __expf(v.x - m) + __expf(v.y - m) + __expf(v.z - m) + __expf(v.w - m);
#pragma unroll
    for (int o = 16; o > 0; o >>= 1)
        sum += __shfl_xor_sync(0xffffffffu, sum, o);

    float lse = m + __logf(sum);
    if (act) {
        *(float4*)&out[(size_t)warp * NC + (lane << 2)] =
            make_float4(v.x - lse, v.y - lse, v.z - lse, v.w - lse);
    }
}

// ---------------------------------------------------------------------------
extern "C" void kernel_launch(void* const* d_in, const int* in_sizes, int n_in,
                              void* d_out, int out_size)
{
    const float* x    = (const float*)d_in[0];
    const int*   er   = (const int*)  d_in[1];
    const int*   ec   = (const int*)  d_in[2];
    const float* ew   = (const float*)d_in[3];
    const float* W1   = (const float*)d_in[4];
    const float* b1   = (const float*)d_in[5];
    const float* W2   = (const float*)d_in[6];
    const float* b2   = (const float*)d_in[7];
    const float* mask = (const float*)d_in[8];
    const int E = in_sizes[1];

    float* out_lsm = (float*)d_out;                   // [N, 40]
    float* out_x2  = (float*)d_out + (size_t)NN * NC; // [N, 128]

    float *supp1, *supp2; float2* edges; int *rowptr, *cursor, *deg;
    cudaGetSymbolAddress((void**)&supp1,  g_supp1);
    cudaGetSymbolAddress((void**)&supp2,  g_supp2);
    cudaGetSymbolAddress((void**)&edges,  g_edges);
    cudaGetSymbolAddress((void**)&rowptr, g_rowptr);
    cudaGetSymbolAddress((void**)&cursor, g_cursor);
    cudaGetSymbolAddress((void**)&deg,    g_deg);

    const bool fork = (g_s1 != nullptr);
    cudaStream_t s1 = fork ? g_s1 : (cudaStream_t)0;

    // Fork: CSR build on side stream, gemm1 on main (null) stream.
    if (fork) {
        cudaEventRecord(g_ev_fork, 0);
        cudaStreamWaitEvent(s1, g_ev_fork, 0);
    }

    zero_deg_kernel<<<(NN + 255) / 256, 256, 0, s1>>>(deg);
    hist_kernel<<<(E / 2 + 255) / 256, 256, 0, s1>>>(er, deg, E);
    scan_kernel<<<1, 1024, 0, s1>>>(deg, rowptr, cursor);
    scatter_kernel<<<(E / 2 + 255) / 256, 256, 0, s1>>>(er, ec, ew, cursor, edges, E);

    gemm1_kernel<<<(NN + 127) / 128, 256>>>(x, W1, supp1);

    // Join before spmm1 (needs both supp1 and CSR).
    if (fork) {
        cudaEventRecord(g_ev_join, s1);
        cudaStreamWaitEvent(0, g_ev_join, 0);
    }

    spmm1_csr_kernel<<<(NN * 32 + 255) / 256, 256>>>(
        rowptr, edges, (const float4*)supp1, b1, mask, out_x2);

    gemm2_kernel<<<(NN + 7) / 8, 256>>>(out_x2, W2, supp2);
    spmm2_lsm_kernel<<<(NN * 32 + 255) / 256, 256>>>(
        rowptr, edges, (const float4*)supp2, b2, out_lsm);
}

// round 10
// speedup vs baseline: 1.1073x; 1.1073x over previous
#include <cuda_runtime.h>
#include <cstdint>

// Problem constants (fixed by the reference)
#define NN 100000
#define NF 512
#define NH 128
#define NC 40
#define EMAX 3200000

// Scratch (device globals; no allocation allowed)
__device__ float  g_supp1[NN * NH];     // x @ W1          51.2 MB
__device__ float  g_supp2[NN * NC];     // x2 @ W2         16 MB
__device__ float2 g_edges[EMAX];        // CSR (col,w)     25.6 MB
__device__ int    g_rowptr[NN + 1];
__device__ int    g_cursor[NN];
__device__ int    g_deg[NN];

// Side stream + fork/join events, created at program init.
static cudaStream_t g_s1 = nullptr;
static cudaEvent_t  g_ev_fork = nullptr, g_ev_join = nullptr;
namespace {
struct StreamInit {
    StreamInit() {
        cudaStreamCreateWithFlags(&g_s1, cudaStreamNonBlocking);
        cudaEventCreateWithFlags(&g_ev_fork, cudaEventDisableTiming);
        cudaEventCreateWithFlags(&g_ev_join, cudaEventDisableTiming);
    }
};
static StreamInit g_stream_init;
}

// ---------------------------------------------------------------------------
// f32x2 packed helpers
// ---------------------------------------------------------------------------
typedef unsigned long long ull;

__device__ __forceinline__ ull ffma2(ull a, ull b, ull c) {
    ull d;
    asm("fma.rn.f32x2 %0, %1, %2, %3;" : "=l"(d) : "l"(a), "l"(b), "l"(c));
    return d;
}
__device__ __forceinline__ ull pack2(float lo, float hi) {
    ull d;
    asm("mov.b64 %0, {%1, %2};" : "=l"(d) : "f"(lo), "f"(hi));
    return d;
}
__device__ __forceinline__ void unpack2(ull v, float& lo, float& hi) {
    asm("mov.b64 {%0, %1}, %2;" : "=f"(lo), "=f"(hi) : "l"(v));
}

// ---------------------------------------------------------------------------
// GEMM1 (packed FFMA2): supp1[N,128] = x[N,512] @ W1[512,128]
// ---------------------------------------------------------------------------
#define AT_PAD 130
#define BS_PAD 132

__global__ __launch_bounds__(256) void gemm1_kernel(
    const float* __restrict__ x, const float* __restrict__ W1,
    float* __restrict__ out)
{
    __shared__ float As_t[16][AT_PAD];   // [k][row]
    __shared__ float Bs[16][BS_PAD];     // [k][col]

    const int t = threadIdx.x;
    const int wid = t >> 5, lane = t & 31;
    const int warp_m = wid & 3;
    const int warp_n = wid >> 2;
    const int r0 = warp_m * 32 + (lane & 3) * 8;
    const int c0 = warp_n * 64 + (lane >> 2) * 8;
    const int block_row = blockIdx.x * 128;

    ull acc[4][8];
#pragma unroll
    for (int p = 0; p < 4; p++)
#pragma unroll
        for (int c = 0; c < 8; c++) acc[p][c] = 0ULL;

    for (int k0 = 0; k0 < NF; k0 += 16) {
#pragma unroll
        for (int j = 0; j < 2; j++) {
            int i = t + j * 256;
            int r = i >> 2;
            int kq = (i & 3) << 2;
            float4 v = make_float4(0.f, 0.f, 0.f, 0.f);
            if (block_row + r < NN)
                v = *(const float4*)&x[(size_t)(block_row + r) * NF + k0 + kq];
            As_t[kq + 0][r] = v.x;
            As_t[kq + 1][r] = v.y;
            As_t[kq + 2][r] = v.z;
            As_t[kq + 3][r] = v.w;
        }
#pragma unroll
        for (int j = 0; j < 2; j++) {
            int i = t + j * 256;
            int kk = i >> 5;
            int c = (i & 31) << 2;
            *(float4*)&Bs[kk][c] = *(const float4*)&W1[(size_t)(k0 + kk) * NH + c];
        }
        __syncthreads();

#pragma unroll
        for (int kk = 0; kk < 16; kk++) {
            ull a2[4];
#pragma unroll
            for (int p = 0; p < 4; p++)
                a2[p] = *(const ull*)&As_t[kk][r0 + p * 2];

            float4 b04 = *(const float4*)&Bs[kk][c0];
            float4 b48 = *(const float4*)&Bs[kk][c0 + 4];
            ull b2[8];
            b2[0] = pack2(b04.x, b04.x); b2[1] = pack2(b04.y, b04.y);
            b2[2] = pack2(b04.z, b04.z); b2[3] = pack2(b04.w, b04.w);
            b2[4] = pack2(b48.x, b48.x); b2[5] = pack2(b48.y, b48.y);
            b2[6] = pack2(b48.z, b48.z); b2[7] = pack2(b48.w, b48.w);

#pragma unroll
            for (int p = 0; p < 4; p++)
#pragma unroll
                for (int c = 0; c < 8; c++)
                    acc[p][c] = ffma2(a2[p], b2[c], acc[p][c]);
        }
        __syncthreads();
    }

#pragma unroll
    for (int p = 0; p < 4; p++) {
        float lo[8], hi[8];
#pragma unroll
        for (int c = 0; c < 8; c++) unpack2(acc[p][c], lo[c], hi[c]);
        int gr0 = block_row + r0 + p * 2;
        int gr1 = gr0 + 1;
        if (gr0 < NN) {
            *(float4*)&out[(size_t)gr0 * NH + c0]     = make_float4(lo[0], lo[1], lo[2], lo[3]);
            *(float4*)&out[(size_t)gr0 * NH + c0 + 4] = make_float4(lo[4], lo[5], lo[6], lo[7]);
        }
        if (gr1 < NN) {
            *(float4*)&out[(size_t)gr1 * NH + c0]     = make_float4(hi[0], hi[1], hi[2], hi[3]);
            *(float4*)&out[(size_t)gr1 * NH + c0 + 4] = make_float4(hi[4], hi[5], hi[6], hi[7]);
        }
    }
}

// ---------------------------------------------------------------------------
// CSR build
// ---------------------------------------------------------------------------
__global__ void zero_deg_kernel(int* __restrict__ deg)
{
    int i = blockIdx.x * blockDim.x + threadIdx.x;
    if (i < NN) deg[i] = 0;
}

__global__ void hist_kernel(const int* __restrict__ er, int* __restrict__ deg, int E)
{
    int e = (blockIdx.x * blockDim.x + threadIdx.x) * 2;
    if (e + 1 < E) {
        int2 r2 = *(const int2*)&er[e];
        atomicAdd(&deg[r2.x], 1);
        atomicAdd(&deg[r2.y], 1);
    } else if (e < E) {
        atomicAdd(&deg[er[e]], 1);
    }
}

// exclusive scan over deg -> rowptr/cursor, single block, warp-shfl based.
__global__ __launch_bounds__(1024) void scan_kernel(
    const int* __restrict__ deg, int* __restrict__ rowptr,
    int* __restrict__ cursor)
{
    __shared__ int wsum[32];
    __shared__ int carry_s;
    const int t = threadIdx.x, lane = t & 31, w = t >> 5;
    if (t == 0) carry_s = 0;
    __syncthreads();

    for (int base = 0; base < NN; base += 4096) {
        int cbase = carry_s;
        int i = base + t * 4;
        int4 v = make_int4(0, 0, 0, 0);
        if (i < NN) v = *(const int4*)&deg[i];   // NN % 4 == 0
        int s = v.x + v.y + v.z + v.w;

        int inc = s;
#pragma unroll
        for (int o = 1; o < 32; o <<= 1) {
            int y = __shfl_up_sync(0xffffffffu, inc, o);
            if (lane >= o) inc += y;
        }
        if (lane == 31) wsum[w] = inc;
        __syncthreads();
        if (w == 0) {
            int ws = wsum[lane];
#pragma unroll
            for (int o = 1; o < 32; o <<= 1) {
                int y = __shfl_up_sync(0xffffffffu, ws, o);
                if (lane >= o) ws += y;
            }
            wsum[lane] = ws;
        }
        __syncthreads();

        int prefix = cbase + ((w > 0) ? wsum[w - 1] : 0) + (inc - s);
        if (i < NN) {
            int e0 = prefix;
            int e1 = e0 + v.x;
            int e2 = e1 + v.y;
            int e3 = e2 + v.z;
            int4 o4 = make_int4(e0, e1, e2, e3);
            *(int4*)&rowptr[i] = o4;
            *(int4*)&cursor[i] = o4;
        }
        __syncthreads();
        if (t == 0) carry_s += wsum[31];
        __syncthreads();
    }
    if (t == 0) rowptr[NN] = carry_s;
}

__global__ void scatter_kernel(
    const int* __restrict__ er, const int* __restrict__ ec,
    const float* __restrict__ ew, int* __restrict__ cursor,
    float2* __restrict__ edges, int E)
{
    int e = (blockIdx.x * blockDim.x + threadIdx.x) * 2;
    if (e + 1 < E) {
        int2   r2 = *(const int2*)&er[e];
        int2   c2 = *(const int2*)&ec[e];
        float2 w2 = *(const float2*)&ew[e];
        int p0 = atomicAdd(&cursor[r2.x], 1);
        edges[p0] = make_float2(__int_as_float(c2.x), w2.x);
        int p1 = atomicAdd(&cursor[r2.y], 1);
        edges[p1] = make_float2(__int_as_float(c2.y), w2.y);
    } else if (e < E) {
        int pos = atomicAdd(&cursor[er[e]], 1);
        edges[pos] = make_float2(__int_as_float(ec[e]), ew[e]);
    }
}

// ---------------------------------------------------------------------------
// SpMM1-CSR fused with bias + relu + dropout mask (4-edge unroll, R6 version)
// ---------------------------------------------------------------------------
__global__ __launch_bounds__(256) void spmm1_csr_kernel(
    const int* __restrict__ rowptr, const float2* __restrict__ edges,
    const float4* __restrict__ suppv, const float* __restrict__ b1,
    const float* __restrict__ mask, float* __restrict__ x2)
{
    const int warp = (blockIdx.x * blockDim.x + threadIdx.x) >> 5;
    if (warp >= NN) return;
    const int lane = threadIdx.x & 31;

    const int s = rowptr[warp];
    const int e = rowptr[warp + 1];

    float4 acc = make_float4(0.f, 0.f, 0.f, 0.f);
    int i = s;
    for (; i + 4 <= e; i += 4) {
        float2 ed0 = __ldg(&edges[i]);
        float2 ed1 = __ldg(&edges[i + 1]);
        float2 ed2 = __ldg(&edges[i + 2]);
        float2 ed3 = __ldg(&edges[i + 3]);
        float4 g0 = __ldg(&suppv[(size_t)__float_as_int(ed0.x) * (NH / 4) + lane]);
        float4 g1 = __ldg(&suppv[(size_t)__float_as_int(ed1.x) * (NH / 4) + lane]);
        float4 g2 = __ldg(&suppv[(size_t)__float_as_int(ed2.x) * (NH / 4) + lane]);
        float4 g3 = __ldg(&suppv[(size_t)__float_as_int(ed3.x) * (NH / 4) + lane]);
        acc.x = fmaf(ed0.y, g0.x, acc.x); acc.y = fmaf(ed0.y, g0.y, acc.y);
        acc.z = fmaf(ed0.y, g0.z, acc.z); acc.w = fmaf(ed0.y, g0.w, acc.w);
        acc.x = fmaf(ed1.y, g1.x, acc.x); acc.y = fmaf(ed1.y, g1.y, acc.y);
        acc.z = fmaf(ed1.y, g1.z, acc.z); acc.w = fmaf(ed1.y, g1.w, acc.w);
        acc.x = fmaf(ed2.y, g2.x, acc.x); acc.y = fmaf(ed2.y, g2.y, acc.y);
        acc.z = fmaf(ed2.y, g2.z, acc.z); acc.w = fmaf(ed2.y, g2.w, acc.w);
        acc.x = fmaf(ed3.y, g3.x, acc.x); acc.y = fmaf(ed3.y, g3.y, acc.y);
        acc.z = fmaf(ed3.y, g3.z, acc.z); acc.w = fmaf(ed3.y, g3.w, acc.w);
    }
    for (; i < e; i++) {
        float2 ed = __ldg(&edges[i]);
        float4 g = __ldg(&suppv[(size_t)__float_as_int(ed.x) * (NH / 4) + lane]);
        acc.x = fmaf(ed.y, g.x, acc.x); acc.y = fmaf(ed.y, g.y, acc.y);
        acc.z = fmaf(ed.y, g.z, acc.z); acc.w = fmaf(ed.y, g.w, acc.w);
    }

    float4 bb = *(const float4*)&b1[lane << 2];
    float4 mm = *(const float4*)&mask[(size_t)warp * NH + (lane << 2)];
    float4 r;
    r.x = fmaxf(acc.x + bb.x, 0.f) * mm.x;
    r.y = fmaxf(acc.y + bb.y, 0.f) * mm.y;
    r.z = fmaxf(acc.z + bb.z, 0.f) * mm.z;
    r.w = fmaxf(acc.w + bb.w, 0.f) * mm.w;
    *(float4*)&x2[(size_t)warp * NH + (lane << 2)] = r;
}

// ---------------------------------------------------------------------------
// GEMM2: supp2[N,40] = x2[N,128] @ W2[128,40]. Warp-per-row, W2 in smem.
// ---------------------------------------------------------------------------
__global__ __launch_bounds__(256) void gemm2_kernel(
    const float* __restrict__ x2, const float* __restrict__ W2,
    float* __restrict__ out)
{
    __shared__ float sW2[NH * NC];  // 20 KB
    for (int i = threadIdx.x; i < NH * NC; i += blockDim.x) sW2[i] = W2[i];
    __syncthreads();

    const int lane = threadIdx.x & 31;
    const int wid  = threadIdx.x >> 5;
    const int row  = blockIdx.x * 8 + wid;
    if (row >= NN) return;

    float acc1 = 0.0f, acc2 = 0.0f;
    const float* xr = &x2[(size_t)row * NH];
#pragma unroll 8
    for (int k = 0; k < NH; k++) {
        float xv = xr[k];
        acc1 = fmaf(xv, sW2[k * NC + lane], acc1);
        if (lane < 8) acc2 = fmaf(xv, sW2[k * NC + 32 + lane], acc2);
    }
    out[(size_t)row * NC + lane] = acc1;
    if (lane < 8) out[(size_t)row * NC + 32 + lane] = acc2;
}

// ---------------------------------------------------------------------------
// SpMM2-CSR fused with bias + log_softmax.
// Lane layout: 3 edge-groups x 10 class-chunks (30 active lanes).
// Group g processes edges s+g, s+g+3, ... -> 3 independent gather chains.
// Fold: BOTH shuffle terms read the PRE-fold accumulator (out-of-range
// shfl_down self-return made the previous two-step fold double lanes 22-29).
// ---------------------------------------------------------------------------
__global__ __launch_bounds__(256) void spmm2_lsm_kernel(
    const int* __restrict__ rowptr, const float2* __restrict__ edges,
    const float4* __restrict__ suppv, const float* __restrict__ b2,
    float* __restrict__ out)
{
    const int warp = (blockIdx.x * blockDim.x + threadIdx.x) >> 5;
    if (warp >= NN) return;
    const int lane = threadIdx.x & 31;
    const int grp  = lane / 10;            // 0,1,2 active; 3 = lanes 30,31 idle
    const int cls  = lane - grp * 10;      // 0..9
    const bool in3 = (grp < 3);

    const int s = rowptr[warp];
    const int e = rowptr[warp + 1];

    float4 acc = make_float4(0.f, 0.f, 0.f, 0.f);
    if (in3) {
        for (int i = s + grp; i < e; i += 3) {
            float2 ed = __ldg(&edges[i]);
            float4 g = __ldg(&suppv[(size_t)__float_as_int(ed.x) * (NC / 4) + cls]);
            acc.x = fmaf(ed.y, g.x, acc.x); acc.y = fmaf(ed.y, g.y, acc.y);
            acc.z = fmaf(ed.y, g.z, acc.z); acc.w = fmaf(ed.y, g.w, acc.w);
        }
    }

    // fold groups 1,2 into lanes 0..9; both terms from the PRE-fold value
    {
        float t1x = __shfl_down_sync(0xffffffffu, acc.x, 10);
        float t1y = __shfl_down_sync(0xffffffffu, acc.y, 10);
        float t1z = __shfl_down_sync(0xffffffffu, acc.z, 10);
        float t1w = __shfl_down_sync(0xffffffffu, acc.w, 10);
        float t2x = __shfl_down_sync(0xffffffffu, acc.x, 20);
        float t2y = __shfl_down_sync(0xffffffffu, acc.y, 20);
        float t2z = __shfl_down_sync(0xffffffffu, acc.z, 20);
        float t2w = __shfl_down_sync(0xffffffffu, acc.w, 20);
        acc.x += t1x + t2x;
        acc.y += t1y + t2y;
        acc.z += t1z + t2z;
        acc.w += t1w + t2w;
    }

    const bool act = (lane < 10);
    float4 v = make_float4(0.f, 0.f, 0.f, 0.f);
    float m = -3.4e38f;
    if (act) {
        float4 bb = *(const float4*)&b2[lane << 2];
        v.x = acc.x + bb.x; v.y = acc.y + bb.y;
        v.z = acc.z + bb.z; v.w = acc.w + bb.w;
        m = fmaxf(fmaxf(v.x, v.y), fmaxf(v.z, v.w));
    }
#pragma unroll
    for (int o = 16; o > 0; o >>= 1)
        m = fmaxf(m, __shfl_xor_sync(0xffffffffu, m, o));

    float sum = 0.f;
    if (act)
        sum = __expf(v.x - m) + __expf(v.y - m) + __expf(v.z - m) + __expf(v.w - m);
#pragma unroll
    for (int o = 16; o > 0; o >>= 1)
        sum += __shfl_xor_sync(0xffffffffu, sum, o);

    float lse = m + __logf(sum);
    if (act) {
        *(float4*)&out[(size_t)warp * NC + (lane << 2)] =
            make_float4(v.x - lse, v.y - lse, v.z - lse, v.w - lse);
    }
}

// ---------------------------------------------------------------------------
extern "C" void kernel_launch(void* const* d_in, const int* in_sizes, int n_in,
                              void* d_out, int out_size)
{
    const float* x    = (const float*)d_in[0];
    const int*   er   = (const int*)  d_in[1];
    const int*   ec   = (const int*)  d_in[2];
    const float* ew   = (const float*)d_in[3];
    const float* W1   = (const float*)d_in[4];
    const float* b1   = (const float*)d_in[5];
    const float* W2   = (const float*)d_in[6];
    const float* b2   = (const float*)d_in[7];
    const float* mask = (const float*)d_in[8];
    const int E = in_sizes[1];

    float* out_lsm = (float*)d_out;                   // [N, 40]
    float* out_x2  = (float*)d_out + (size_t)NN * NC; // [N, 128]

    float *supp1, *supp2; float2* edges; int *rowptr, *cursor, *deg;
    cudaGetSymbolAddress((void**)&supp1,  g_supp1);
    cudaGetSymbolAddress((void**)&supp2,  g_supp2);
    cudaGetSymbolAddress((void**)&edges,  g_edges);
    cudaGetSymbolAddress((void**)&rowptr, g_rowptr);
    cudaGetSymbolAddress((void**)&cursor, g_cursor);
    cudaGetSymbolAddress((void**)&deg,    g_deg);

    const bool fork = (g_s1 != nullptr);
    cudaStream_t s1 = fork ? g_s1 : (cudaStream_t)0;

    // Fork: CSR build on side stream, gemm1 on main (null) stream.
    if (fork) {
        cudaEventRecord(g_ev_fork, 0);
        cudaStreamWaitEvent(s1, g_ev_fork, 0);
    }

    zero_deg_kernel<<<(NN + 255) / 256, 256, 0, s1>>>(deg);
    hist_kernel<<<(E / 2 + 255) / 256, 256, 0, s1>>>(er, deg, E);
    scan_kernel<<<1, 1024, 0, s1>>>(deg, rowptr, cursor);
    scatter_kernel<<<(E / 2 + 255) / 256, 256, 0, s1>>>(er, ec, ew, cursor, edges, E);

    gemm1_kernel<<<(NN + 127) / 128, 256>>>(x, W1, supp1);

    // Join before spmm1 (needs both supp1 and CSR).
    if (fork) {
        cudaEventRecord(g_ev_join, s1);
        cudaStreamWaitEvent(0, g_ev_join, 0);
    }

    spmm1_csr_kernel<<<(NN * 32 + 255) / 256, 256>>>(
        rowptr, edges, (const float4*)supp1, b1, mask, out_x2);

    gemm2_kernel<<<(NN + 7) / 8, 256>>>(out_x2, W2, supp2);
    spmm2_lsm_kernel<<<(NN * 32 + 255) / 256, 256>>>(
        rowptr, edges, (const float4*)supp2, b2, out_lsm);
}